// round 11
// baseline (speedup 1.0000x reference)
#include <cuda_runtime.h>
#include <math.h>

// ---------------------------------------------------------------------------
// Problem constants
// ---------------------------------------------------------------------------
namespace {
constexpr int kC = 32, kG = 8, kD = 32, kH = 192, kW = 192;
constexpr int kHW = kH * kW;
constexpr int kNS = 4;   // nsrc = V-1

// padded src layout: 1-pixel zero border on each side
constexpr int kWP = kW + 2;              // 194
constexpr int kHP = kH + 2;              // 194
constexpr int kRS = kWP * kC;            // row stride (floats)
constexpr int kVS = kHP * kWP * kC;      // view stride (floats)

// output layout (concatenated tuple, all f32)
constexpr int OFF_DEPTH = 0;
constexpr int OFF_CONF  = OFF_DEPTH + kHW;
constexpr int OFF_ATTN  = OFF_CONF + kHW;            // (D,H,W)
constexpr int OFF_EN    = OFF_ATTN + kD * kHW;       // (3,H,W)
constexpr int OFF_SW    = OFF_EN + 3 * kHW;          // (H,W)
constexpr int OFF_WT    = OFF_SW + kHW;              // (NS,H,W)
constexpr int OFF_NV    = OFF_WT + kNS * kHW;        // (D,H,W)
constexpr int OFF_MIN   = OFF_NV + kD * kHW;         // (H,W)
constexpr int OFF_MAX   = OFF_MIN + kHW;             // (H,W)
}

// ---------------------------------------------------------------------------
// Scratch (static __device__ arrays: no allocation allowed)
// ---------------------------------------------------------------------------
__device__ float g_ref_t[kHW * kC];              // ref features (H,W,C)
__device__ float g_src_p[kNS * kVS];             // src features padded (ns,HP,WP,C)
__device__ float g_rot[kNS * 9];
__device__ float g_trans[kNS * 3];
__device__ float g_norv[kNS * 3];
__device__ unsigned g_min_enc, g_max_enc;

// order-preserving float<->uint encoding (for atomic min/max)
__device__ __forceinline__ unsigned enc_f(float x) {
    unsigned u = __float_as_uint(x);
    return (u & 0x80000000u) ? ~u : (u | 0x80000000u);
}
__device__ __forceinline__ float dec_f(unsigned u) {
    return (u & 0x80000000u) ? __uint_as_float(u & 0x7FFFFFFFu)
                             : __uint_as_float(~u);
}

// ---------------------------------------------------------------------------
// Setup: projection matrices, relative rotations, min/max init (1 thread)
// ---------------------------------------------------------------------------
__device__ void inv3(const double* a, double* o) {
    double c00 =   a[4]*a[8] - a[5]*a[7];
    double c01 = -(a[3]*a[8] - a[5]*a[6]);
    double c02 =   a[3]*a[7] - a[4]*a[6];
    double det = a[0]*c00 + a[1]*c01 + a[2]*c02;
    double id = 1.0 / det;
    o[0] =  c00 * id;
    o[1] = -(a[1]*a[8] - a[2]*a[7]) * id;
    o[2] =  (a[1]*a[5] - a[2]*a[4]) * id;
    o[3] =  c01 * id;
    o[4] =  (a[0]*a[8] - a[2]*a[6]) * id;
    o[5] = -(a[0]*a[5] - a[2]*a[3]) * id;
    o[6] =  c02 * id;
    o[7] = -(a[0]*a[7] - a[1]*a[6]) * id;
    o[8] =  (a[0]*a[4] - a[1]*a[3]) * id;
}
__device__ void mm3(const double* a, const double* b, double* o) {
    for (int r = 0; r < 3; r++)
        for (int c = 0; c < 3; c++)
            o[r*3+c] = a[r*3]*b[c] + a[r*3+1]*b[3+c] + a[r*3+2]*b[6+c];
}

__global__ void setup_kernel(const float* __restrict__ rotation,
                             const float* __restrict__ proj) {
    if (threadIdx.x != 0 || blockIdx.x != 0) return;
    g_min_enc = 0xFFFFFFFFu;
    g_max_enc = 0u;
    // proj layout: (1, 5, 2, 4, 4) : [view][E|K][4][4]
    // M_v = K33 @ E33 ; t_v = K33 @ E[:3,3]
    double M[5][9], t[5][3];
    for (int v = 0; v < 5; v++) {
        const float* E = proj + v * 32;
        const float* K = proj + v * 32 + 16;
        for (int r = 0; r < 3; r++) {
            for (int c = 0; c < 3; c++) {
                double s = 0.0;
                for (int k = 0; k < 3; k++) s += (double)K[r*4+k] * (double)E[k*4+c];
                M[v][r*3+c] = s;
            }
            double s = 0.0;
            for (int k = 0; k < 3; k++) s += (double)K[r*4+k] * (double)E[k*4+3];
            t[v][r] = s;
        }
    }
    double MrI[9]; inv3(M[0], MrI);
    double R0[9];  for (int i = 0; i < 9; i++) R0[i] = (double)rotation[i];
    double R0I[9]; inv3(R0, R0I);
    for (int s = 0; s < kNS; s++) {
        int v = s + 1;
        // proj = src_new @ inv(ref_new): rot = Ms Mr^-1, trans = ts - rot tr
        double R[9]; mm3(M[v], MrI, R);
        for (int i = 0; i < 9; i++) g_rot[s*9+i] = (float)R[i];
        for (int r = 0; r < 3; r++) {
            double tr = t[v][r];
            for (int c = 0; c < 3; c++) tr -= R[r*3+c] * t[0][c];
            g_trans[s*3+r] = (float)tr;
        }
        // norv = row 2 of (R_v @ R_0^-1)
        double Rv[9]; for (int i = 0; i < 9; i++) Rv[i] = (double)rotation[v*9+i];
        double Rel[9]; mm3(Rv, R0I, Rel);
        for (int c = 0; c < 3; c++) g_norv[s*3+c] = (float)Rel[6+c];
    }
}

// ---------------------------------------------------------------------------
// Zero the 1-pixel border of the padded src arrays (4 views).
// border pixels per view: y in {0, HP-1} full rows + x in {0, WP-1} cols.
// ---------------------------------------------------------------------------
__global__ void border_kernel() {
    constexpr int NB = 2 * kWP + 2 * (kHP - 2);   // 772 border pixels per view
    int i = blockIdx.x * blockDim.x + threadIdx.x;
    int c = i & 31;
    int b = (i >> 5) % NB;
    int v = (i >> 5) / NB;
    if (v >= kNS) return;
    int y, x;
    if (b < kWP)               { y = 0;          x = b; }
    else if (b < 2 * kWP)      { y = kHP - 1;    x = b - kWP; }
    else if (b < 2*kWP + kHP-2){ y = b - 2*kWP + 1;       x = 0; }
    else                       { y = b - (2*kWP + kHP-2) + 1; x = kWP - 1; }
    g_src_p[v * kVS + (y * kWP + x) * kC + c] = 0.f;
}

// ---------------------------------------------------------------------------
// Transpose features (C,H,W) -> padded (H,W,C), 5 views. Coalesced both sides.
// ---------------------------------------------------------------------------
__global__ void transpose_kernel(const float* __restrict__ ref,
                                 const float* __restrict__ src) {
    __shared__ float tile[32][33];
    int v = blockIdx.z;
    const float* in = (v == 0) ? ref : (src + (size_t)(v - 1) * kC * kHW);
    int wbase = blockIdx.x * 32;
    int h = blockIdx.y;
    int tx = threadIdx.x, ty = threadIdx.y;   // ty = channel on read
    tile[ty][tx] = in[(size_t)ty * kHW + h * kW + wbase + tx];
    __syncthreads();
    if (v == 0) {
        g_ref_t[(size_t)(h * kW + wbase + ty) * kC + tx] = tile[tx][ty];
    } else {
        g_src_p[(size_t)(v - 1) * kVS +
                ((h + 1) * kWP + (wbase + ty + 1)) * kC + tx] = tile[tx][ty];
    }
}

// ---------------------------------------------------------------------------
// hmin / hmax reduction over depth_hypo
// ---------------------------------------------------------------------------
__global__ void minmax_kernel(const float* __restrict__ dh) {
    __shared__ unsigned smn[256], smx[256];
    unsigned lmn = 0xFFFFFFFFu, lmx = 0u;
    for (int i = blockIdx.x * blockDim.x + threadIdx.x; i < kD * kHW;
         i += gridDim.x * blockDim.x) {
        unsigned e = enc_f(dh[i]);
        lmn = min(lmn, e);
        lmx = max(lmx, e);
    }
    smn[threadIdx.x] = lmn; smx[threadIdx.x] = lmx;
    __syncthreads();
    for (int s = 128; s > 0; s >>= 1) {
        if (threadIdx.x < s) {
            smn[threadIdx.x] = min(smn[threadIdx.x], smn[threadIdx.x + s]);
            smx[threadIdx.x] = max(smx[threadIdx.x], smx[threadIdx.x + s]);
        }
        __syncthreads();
    }
    if (threadIdx.x == 0) {
        atomicMin(&g_min_enc, smn[0]);
        atomicMax(&g_max_enc, smx[0]);
    }
}

// ---------------------------------------------------------------------------
// Main fused kernel: one warp per pixel, lane = channel (C=32), D=32=warpSize
//
// Zero-padded src + coordinate clamp to [-1, W]/[-1, H] makes every OOB tap
// either land in the zero border or carry weight 0 -> no bounds predicates.
// cor_feats is never output; only
//   logit_d = [ Sum_s factor_s * e_sd * swd_s * (Sum_g wreg_g * cfd_sdg) ]
//             / (sumw_d * cws_d) + norm_hypo_d
// ---------------------------------------------------------------------------
__global__ __launch_bounds__(128, 8) void main_kernel(
    const float* __restrict__ normal_plane,
    const float* __restrict__ depth_hypo,
    const float* __restrict__ w_reg,
    const float* __restrict__ w_norm,
    float* __restrict__ out)
{
    const unsigned FULL = 0xFFFFFFFFu;
    int p = blockIdx.x * 4 + (threadIdx.x >> 5);
    int lane = threadIdx.x & 31;
    float xf = (float)(p % kW), yf = (float)(p / kW);

    float refc4 = g_ref_t[p * kC + lane] * 0.25f;  // ref feature * 1/4 (group mean prefold)
    float np0 = normal_plane[p];
    float np1 = normal_plane[kHW + p];
    float np2 = normal_plane[2 * kHW + p];
    float wreg_g = w_reg[lane >> 2];
    float dep_lane = depth_hypo[lane * kHW + p];   // lane l holds depth l

    float Lacc      = 0.f;     // numerator of attn logit, d = lane
    float cws_lane  = 1e-8f;   // cor_weight_sum[d=lane]
    float sumw_lane = 1e-8f;   // sum_weight[d=lane]
    float nv_lane   = 0.f;     // num_valid[d=lane]

#pragma unroll 1
    for (int s = 0; s < kNS; s++) {
        // pointer pre-offset so index math is (y0*kWP + x0)*kC with y0,x0 in [-1,..]
        const float* srcL = g_src_p + s * kVS + (kWP + 1) * kC + lane;
        float r00 = g_rot[s*9+0], r01 = g_rot[s*9+1], r02 = g_rot[s*9+2];
        float r10 = g_rot[s*9+3], r11 = g_rot[s*9+4], r12 = g_rot[s*9+5];
        float r20 = g_rot[s*9+6], r21 = g_rot[s*9+7], r22 = g_rot[s*9+8];
        float trx = g_trans[s*3+0], try_ = g_trans[s*3+1], trz = g_trans[s*3+2];
        float rx = r00*xf + r01*yf + r02;
        float ry = r10*xf + r11*yf + r12;
        float rz = r20*xf + r21*yf + r22;
        float nv0 = g_norv[s*3+0], nv1 = g_norv[s*3+1], nv2 = g_norv[s*3+2];
        float srcw = fmaxf(np0*nv0 + np1*nv1 + np2*nv2, 0.f) + 0.01f;

        float den = 0.f;       // per-src softmax denominator (max-free; logits O(10))
        float my_e = 0.f;      // e_d at d == lane
        float P = 0.f;         // e_d * q_d at d == lane (validity applied post-loop)
        unsigned vmask = 0u;   // valid bits, built on lane 0 only

#pragma unroll
        for (int d = 0; d < kD; d++) {
            float dep = __shfl_sync(FULL, dep_lane, d);
            float X = fmaf(rx, dep, trx);
            float Y = fmaf(ry, dep, try_);
            float Z = fmaf(rz, dep, trz);
            if (Z == 0.f) Z = 1e-9f;
            float rZ = __fdividef(1.f, Z);
            // clamp into padded range: OOB taps hit the zero border or get w=0
            float px = fminf(fmaxf(X * rZ, -1.f), (float)kW);
            float py = fminf(fmaxf(Y * rZ, -1.f), (float)kH);
            float x0f = floorf(px), y0f = floorf(py);
            float wx = px - x0f, wy = py - y0f;
            int x0 = (int)x0f, y0 = (int)y0f;          // in [-1, kW]/[-1, kH]
            int base = y0 * kRS + x0 * kC;
            float owx = 1.f - wx, owy = 1.f - wy;
            float acc;
            acc = (owx * owy) * srcL[base];
            acc = fmaf(wx  * owy, srcL[base + kC],       acc);
            acc = fmaf(owx * wy,  srcL[base + kRS],      acc);
            acc = fmaf(wx  * wy,  srcL[base + kRS + kC], acc);
            // validity bit on lane 0 only (channel 0); broadcast after the loop
            if (lane == 0) vmask |= (acc != 0.f) ? (1u << d) : 0u;
            // grouped correlation: prefolded mean over 4 channels in my group
            float prod = acc * refc4;
            prod += __shfl_xor_sync(FULL, prod, 1);
            prod += __shfl_xor_sync(FULL, prod, 2);
            // cfd = prod (group value). Two group trees:
            //   ts = Sum_g cfd (softmax logit), qv = Sum_g wreg_g*cfd (attn numerator)
            float ts = prod;
            float qv = prod * wreg_g;
            ts += __shfl_xor_sync(FULL, ts, 4);
            qv += __shfl_xor_sync(FULL, qv, 4);
            ts += __shfl_xor_sync(FULL, ts, 8);
            qv += __shfl_xor_sync(FULL, qv, 8);
            ts += __shfl_xor_sync(FULL, ts, 16);
            qv += __shfl_xor_sync(FULL, qv, 16);
            float e = __expf(ts);     // logits O(+-10): no max-subtract needed
            den += e;
            if (lane == d) {
                my_e = e;
                P = e * qv;
            }
        }
        vmask = __shfl_sync(FULL, vmask, 0);

        float factor = 0.17677669529663687f / den;  // (1/sqrt(C)) / den  (precise)
        cws_lane += my_e * factor;
        float mybit = (float)((vmask >> lane) & 1u);
        sumw_lane += srcw * mybit;
        nv_lane += mybit;
        Lacc = fmaf(P * mybit, factor * srcw, Lacc);
        // sims[s] = mean over D of src_w * valid
        if (lane == 0)
            out[OFF_WT + s * kHW + p] = srcw * (float)__popc(vmask) * (1.f / kD);
    }

    // ---------------- final per-pixel stage ----------------
    float hmin = dec_f(g_min_enc), hmax = dec_f(g_max_enc);
    float nh_lane = (dep_lane - hmin) / (hmax - hmin);

    // qv tree summed over 32 lanes = 4x the 8-group sum -> *0.25
    // precise two-step division matching reference (/sum_weight then /cor_weight_sum)
    float logit_lane = (Lacc * 0.25f / sumw_lane) / cws_lane + nh_lane;

    // softmax over depth (precise; once per pixel)
    float m2 = logit_lane;
#pragma unroll
    for (int off = 16; off > 0; off >>= 1)
        m2 = fmaxf(m2, __shfl_xor_sync(FULL, m2, off));
    float e2 = expf(logit_lane - m2);
    float den2 = e2;
#pragma unroll
    for (int off = 16; off > 0; off >>= 1)
        den2 += __shfl_xor_sync(FULL, den2, off);
    float aw = e2 / den2;
    out[OFF_ATTN + lane * kHW + p] = aw;
    out[OFF_NV + lane * kHW + p] = nv_lane;

    // argmax (first index on tie, matching jnp.argmax)
    float bv = aw; int bi = lane;
#pragma unroll
    for (int off = 16; off > 0; off >>= 1) {
        float ov = __shfl_xor_sync(FULL, bv, off);
        int oi = __shfl_xor_sync(FULL, bi, off);
        if (ov > bv || (ov == bv && oi < bi)) { bv = ov; bi = oi; }
    }
    float depth = __shfl_sync(FULL, dep_lane, bi);
    float d0 = __shfl_sync(FULL, dep_lane, 0);
    float d1 = __shfl_sync(FULL, dep_lane, 1);
    float sw0 = __shfl_sync(FULL, sumw_lane, 0);
    if (lane == 0) {
        out[OFF_DEPTH + p] = depth;
        out[OFF_CONF + p] = bv;
        out[OFF_SW + p] = sw0 * 0.25f;   // / nsrc
        float itv = d1 - d0;
        out[OFF_MIN + p] = depth - itv;
        out[OFF_MAX + p] = depth + itv;
    }
    if (lane < 3) {
        out[OFF_EN + lane * kHW + p] =
            w_norm[lane*3+0]*np0 + w_norm[lane*3+1]*np1 + w_norm[lane*3+2]*np2;
    }
}

// ---------------------------------------------------------------------------
extern "C" void kernel_launch(void* const* d_in, const int* in_sizes, int n_in,
                              void* d_out, int out_size) {
    const float* ref   = (const float*)d_in[0];  // (1,32,192,192)
    const float* src   = (const float*)d_in[1];  // (4,1,32,192,192)
    const float* rotn  = (const float*)d_in[2];  // (1,5,3,3)
    const float* normp = (const float*)d_in[3];  // (1,3,192,192)
    const float* projm = (const float*)d_in[4];  // (1,5,2,4,4)
    const float* dhypo = (const float*)d_in[5];  // (1,32,192,192)
    const float* wreg  = (const float*)d_in[6];  // (8,)
    const float* wnorm = (const float*)d_in[7];  // (3,3)
    float* out = (float*)d_out;

    setup_kernel<<<1, 1>>>(rotn, projm);
    {
        constexpr int NB = 2 * kWP + 2 * (kHP - 2);
        int total = kNS * NB * 32;
        border_kernel<<<(total + 255) / 256, 256>>>();
    }
    dim3 tb(32, 32);
    dim3 tg(kW / 32, kH, 5);
    transpose_kernel<<<tg, tb>>>(ref, src);
    minmax_kernel<<<256, 256>>>(dhypo);
    main_kernel<<<kHW / 4, 128>>>(normp, dhypo, wreg, wnorm, out);
}

// round 13
// speedup vs baseline: 1.6404x; 1.6404x over previous
#include <cuda_runtime.h>
#include <math.h>

// ---------------------------------------------------------------------------
// Problem constants
// ---------------------------------------------------------------------------
namespace {
constexpr int kC = 32, kG = 8, kD = 32, kH = 192, kW = 192;
constexpr int kHW = kH * kW;
constexpr int kNS = 4;   // nsrc = V-1

// output layout (concatenated tuple, all f32)
constexpr int OFF_DEPTH = 0;
constexpr int OFF_CONF  = OFF_DEPTH + kHW;
constexpr int OFF_ATTN  = OFF_CONF + kHW;            // (D,H,W)
constexpr int OFF_EN    = OFF_ATTN + kD * kHW;       // (3,H,W)
constexpr int OFF_SW    = OFF_EN + 3 * kHW;          // (H,W)
constexpr int OFF_WT    = OFF_SW + kHW;              // (NS,H,W)
constexpr int OFF_NV    = OFF_WT + kNS * kHW;        // (D,H,W)
constexpr int OFF_MIN   = OFF_NV + kD * kHW;         // (H,W)
constexpr int OFF_MAX   = OFF_MIN + kHW;             // (H,W)
}

// ---------------------------------------------------------------------------
// Scratch (static __device__ arrays: no allocation allowed)
// ---------------------------------------------------------------------------
__device__ float g_ref_t[kHW * kC];              // ref features (H,W,C)
__device__ float g_src_t[kNS * kHW * kC];        // src features (ns,H,W,C)
__device__ float g_rot[kNS * 9];
__device__ float g_trans[kNS * 3];
__device__ float g_norv[kNS * 3];
__device__ unsigned g_min_enc, g_max_enc;

// order-preserving float<->uint encoding (for atomic min/max)
__device__ __forceinline__ unsigned enc_f(float x) {
    unsigned u = __float_as_uint(x);
    return (u & 0x80000000u) ? ~u : (u | 0x80000000u);
}
__device__ __forceinline__ float dec_f(unsigned u) {
    return (u & 0x80000000u) ? __uint_as_float(u & 0x7FFFFFFFu)
                             : __uint_as_float(~u);
}

// ---------------------------------------------------------------------------
// Setup: projection matrices, relative rotations, min/max init (1 thread)
// ---------------------------------------------------------------------------
__device__ void inv3(const double* a, double* o) {
    double c00 =   a[4]*a[8] - a[5]*a[7];
    double c01 = -(a[3]*a[8] - a[5]*a[6]);
    double c02 =   a[3]*a[7] - a[4]*a[6];
    double det = a[0]*c00 + a[1]*c01 + a[2]*c02;
    double id = 1.0 / det;
    o[0] =  c00 * id;
    o[1] = -(a[1]*a[8] - a[2]*a[7]) * id;
    o[2] =  (a[1]*a[5] - a[2]*a[4]) * id;
    o[3] =  c01 * id;
    o[4] =  (a[0]*a[8] - a[2]*a[6]) * id;
    o[5] = -(a[0]*a[5] - a[2]*a[3]) * id;
    o[6] =  c02 * id;
    o[7] = -(a[0]*a[7] - a[1]*a[6]) * id;
    o[8] =  (a[0]*a[4] - a[1]*a[3]) * id;
}
__device__ void mm3(const double* a, const double* b, double* o) {
    for (int r = 0; r < 3; r++)
        for (int c = 0; c < 3; c++)
            o[r*3+c] = a[r*3]*b[c] + a[r*3+1]*b[3+c] + a[r*3+2]*b[6+c];
}

__global__ void setup_kernel(const float* __restrict__ rotation,
                             const float* __restrict__ proj) {
    if (threadIdx.x != 0 || blockIdx.x != 0) return;
    g_min_enc = 0xFFFFFFFFu;
    g_max_enc = 0u;
    // proj layout: (1, 5, 2, 4, 4) : [view][E|K][4][4]
    // M_v = K33 @ E33 ; t_v = K33 @ E[:3,3]
    double M[5][9], t[5][3];
    for (int v = 0; v < 5; v++) {
        const float* E = proj + v * 32;
        const float* K = proj + v * 32 + 16;
        for (int r = 0; r < 3; r++) {
            for (int c = 0; c < 3; c++) {
                double s = 0.0;
                for (int k = 0; k < 3; k++) s += (double)K[r*4+k] * (double)E[k*4+c];
                M[v][r*3+c] = s;
            }
            double s = 0.0;
            for (int k = 0; k < 3; k++) s += (double)K[r*4+k] * (double)E[k*4+3];
            t[v][r] = s;
        }
    }
    double MrI[9]; inv3(M[0], MrI);
    double R0[9];  for (int i = 0; i < 9; i++) R0[i] = (double)rotation[i];
    double R0I[9]; inv3(R0, R0I);
    for (int s = 0; s < kNS; s++) {
        int v = s + 1;
        // proj = src_new @ inv(ref_new): rot = Ms Mr^-1, trans = ts - rot tr
        double R[9]; mm3(M[v], MrI, R);
        for (int i = 0; i < 9; i++) g_rot[s*9+i] = (float)R[i];
        for (int r = 0; r < 3; r++) {
            double tr = t[v][r];
            for (int c = 0; c < 3; c++) tr -= R[r*3+c] * t[0][c];
            g_trans[s*3+r] = (float)tr;
        }
        // norv = row 2 of (R_v @ R_0^-1)
        double Rv[9]; for (int i = 0; i < 9; i++) Rv[i] = (double)rotation[v*9+i];
        double Rel[9]; mm3(Rv, R0I, Rel);
        for (int c = 0; c < 3; c++) g_norv[s*3+c] = (float)Rel[6+c];
    }
}

// ---------------------------------------------------------------------------
// Transpose features (C,H,W) -> (H,W,C), 5 views. Coalesced both sides.
// ---------------------------------------------------------------------------
__global__ void transpose_kernel(const float* __restrict__ ref,
                                 const float* __restrict__ src) {
    __shared__ float tile[32][33];
    int v = blockIdx.z;
    const float* in = (v == 0) ? ref : (src + (size_t)(v - 1) * kC * kHW);
    float* out = (v == 0) ? g_ref_t : (g_src_t + (size_t)(v - 1) * kHW * kC);
    int wbase = blockIdx.x * 32;
    int h = blockIdx.y;
    int tx = threadIdx.x, ty = threadIdx.y;   // ty = channel on read
    tile[ty][tx] = in[(size_t)ty * kHW + h * kW + wbase + tx];
    __syncthreads();
    out[(size_t)(h * kW + wbase + ty) * kC + tx] = tile[tx][ty];
}

// ---------------------------------------------------------------------------
// hmin / hmax reduction over depth_hypo
// ---------------------------------------------------------------------------
__global__ void minmax_kernel(const float* __restrict__ dh) {
    __shared__ unsigned smn[256], smx[256];
    unsigned lmn = 0xFFFFFFFFu, lmx = 0u;
    for (int i = blockIdx.x * blockDim.x + threadIdx.x; i < kD * kHW;
         i += gridDim.x * blockDim.x) {
        unsigned e = enc_f(dh[i]);
        lmn = min(lmn, e);
        lmx = max(lmx, e);
    }
    smn[threadIdx.x] = lmn; smx[threadIdx.x] = lmx;
    __syncthreads();
    for (int s = 128; s > 0; s >>= 1) {
        if (threadIdx.x < s) {
            smn[threadIdx.x] = min(smn[threadIdx.x], smn[threadIdx.x + s]);
            smx[threadIdx.x] = max(smx[threadIdx.x], smx[threadIdx.x + s]);
        }
        __syncthreads();
    }
    if (threadIdx.x == 0) {
        atomicMin(&g_min_enc, smn[0]);
        atomicMax(&g_max_enc, smx[0]);
    }
}

// ---------------------------------------------------------------------------
// Main fused kernel: one warp per pixel, lane = channel (C=32), D=32=warpSize
//
// The projection math is warp-uniform per depth d, so each lane l precomputes
// the sample descriptor for ITS OWN depth l once per source (lane=depth),
// packed into one int:
//   bits [0:21)  base = (yclip0*kW + xclip0)*kC   (< 2^21)
//   bit  21      dxc  = xclip1 - xclip0 (0/1)
//   bit  22      dyc  = yclip1 - yclip0 (0/1)
//   bits 23..26  tap validity v00,v01,v10,v11 (reference clip+zero-weight)
// The depth loop broadcasts {pb, wx, wy} (3 shfls) instead of recomputing
// ~27 uniform ops (incl. MUFU.RCP) per iteration.
// ---------------------------------------------------------------------------
__global__ __launch_bounds__(128, 8) void main_kernel(
    const float* __restrict__ normal_plane,
    const float* __restrict__ depth_hypo,
    const float* __restrict__ w_reg,
    const float* __restrict__ w_norm,
    float* __restrict__ out)
{
    const unsigned FULL = 0xFFFFFFFFu;
    int p = blockIdx.x * 4 + (threadIdx.x >> 5);
    int lane = threadIdx.x & 31;
    float xf = (float)(p % kW), yf = (float)(p / kW);

    float refc4 = g_ref_t[p * kC + lane] * 0.25f;  // ref feature * 1/4 (group mean prefold)
    float np0 = normal_plane[p];
    float np1 = normal_plane[kHW + p];
    float np2 = normal_plane[2 * kHW + p];
    float wreg_g = w_reg[lane >> 2];
    float dep_lane = depth_hypo[lane * kHW + p];   // lane l holds depth l

    float Lacc      = 0.f;     // numerator of attn logit, d = lane
    float cws_lane  = 1e-8f;   // cor_weight_sum[d=lane]
    float sumw_lane = 1e-8f;   // sum_weight[d=lane]
    float nv_lane   = 0.f;     // num_valid[d=lane]

#pragma unroll 1
    for (int s = 0; s < kNS; s++) {
        const float* srcL = g_src_t + s * (kHW * kC) + lane;
        float nv0 = g_norv[s*3+0], nv1 = g_norv[s*3+1], nv2 = g_norv[s*3+2];
        float srcw = fmaxf(np0*nv0 + np1*nv1 + np2*nv2, 0.f) + 0.01f;

        // ---- per-lane projection precompute (my depth = lane) ----
        int   pb;
        float wx_l, wy_l;
        {
            float r00 = g_rot[s*9+0], r01 = g_rot[s*9+1], r02 = g_rot[s*9+2];
            float r10 = g_rot[s*9+3], r11 = g_rot[s*9+4], r12 = g_rot[s*9+5];
            float r20 = g_rot[s*9+6], r21 = g_rot[s*9+7], r22 = g_rot[s*9+8];
            float trx = g_trans[s*3+0], try_ = g_trans[s*3+1], trz = g_trans[s*3+2];
            float rx = r00*xf + r01*yf + r02;
            float ry = r10*xf + r11*yf + r12;
            float rz = r20*xf + r21*yf + r22;
            float X = fmaf(rx, dep_lane, trx);
            float Y = fmaf(ry, dep_lane, try_);
            float Z = fmaf(rz, dep_lane, trz);
            if (Z == 0.f) Z = 1e-9f;
            float rZ = __fdividef(1.f, Z);
            // clamp to avoid int overflow; preserves in/out-of-bounds semantics
            float px = fminf(fmaxf(X * rZ, -4.f), (float)kW + 4.f);
            float py = fminf(fmaxf(Y * rZ, -4.f), (float)kH + 4.f);
            float x0f = floorf(px), y0f = floorf(py);
            wx_l = px - x0f;
            wy_l = py - y0f;
            int x0 = (int)x0f, y0 = (int)y0f;
            int x1 = x0 + 1, y1 = y0 + 1;
            bool bx0 = (unsigned)x0 < (unsigned)kW;
            bool bx1 = (unsigned)x1 < (unsigned)kW;
            bool by0 = (unsigned)y0 < (unsigned)kH;
            bool by1 = (unsigned)y1 < (unsigned)kH;
            int xc0 = min(max(x0, 0), kW - 1), xc1 = min(max(x1, 0), kW - 1);
            int yc0 = min(max(y0, 0), kH - 1), yc1 = min(max(y1, 0), kH - 1);
            pb = (yc0 * kW + xc0) * kC
               | ((xc1 - xc0) << 21) | ((yc1 - yc0) << 22)
               | ((bx0 && by0) ? 1 << 23 : 0)
               | ((bx1 && by0) ? 1 << 24 : 0)
               | ((bx0 && by1) ? 1 << 25 : 0)
               | ((bx1 && by1) ? 1 << 26 : 0);
        }

        float den = 0.f;       // per-src softmax denominator (max-free; logits O(10))
        float my_e = 0.f;      // e_d at d == lane
        float P = 0.f;         // e_d * q_d at d == lane (validity applied post-loop)
        unsigned vmask = 0u;   // valid bits, built on lane 0 only

#pragma unroll
        for (int d = 0; d < kD; d++) {
            int   b  = __shfl_sync(FULL, pb, d);
            float wx = __shfl_sync(FULL, wx_l, d);
            float wy = __shfl_sync(FULL, wy_l, d);
            int a00  = b & 0x1FFFFF;
            int offx = (b >> 16) & 32;            // dxc * kC   (bit21 -> 32)
            int offy = ((b >> 11) & 2048) * 3;    // dyc * kW*kC (bit22 -> 6144)
            float owx = 1.f - wx, owy = 1.f - wy;
            float acc = 0.f;
            if (b & (1 << 23)) acc = fmaf(owx * owy, srcL[a00], acc);
            if (b & (1 << 24)) acc = fmaf(wx  * owy, srcL[a00 + offx], acc);
            if (b & (1 << 25)) acc = fmaf(owx * wy,  srcL[a00 + offy], acc);
            if (b & (1 << 26)) acc = fmaf(wx  * wy,  srcL[a00 + offy + offx], acc);
            // validity bit on lane 0 only (channel 0); broadcast after the loop
            if (lane == 0) vmask |= (acc != 0.f) ? (1u << d) : 0u;
            // grouped correlation: prefolded mean over 4 channels in my group
            float prod = acc * refc4;
            prod += __shfl_xor_sync(FULL, prod, 1);
            prod += __shfl_xor_sync(FULL, prod, 2);
            // cfd = prod (group value). Two group trees:
            //   ts = Sum_g cfd (softmax logit), qv = Sum_g wreg_g*cfd (attn numerator)
            float ts = prod;
            float qv = prod * wreg_g;
            ts += __shfl_xor_sync(FULL, ts, 4);
            qv += __shfl_xor_sync(FULL, qv, 4);
            ts += __shfl_xor_sync(FULL, ts, 8);
            qv += __shfl_xor_sync(FULL, qv, 8);
            ts += __shfl_xor_sync(FULL, ts, 16);
            qv += __shfl_xor_sync(FULL, qv, 16);
            float e = __expf(ts);     // logits O(+-10): no max-subtract needed
            den += e;
            if (lane == d) {
                my_e = e;
                P = e * qv;
            }
        }
        vmask = __shfl_sync(FULL, vmask, 0);

        float factor = 0.17677669529663687f / den;  // (1/sqrt(C)) / den  (precise)
        cws_lane += my_e * factor;
        float mybit = (float)((vmask >> lane) & 1u);
        sumw_lane += srcw * mybit;
        nv_lane += mybit;
        Lacc = fmaf(P * mybit, factor * srcw, Lacc);
        // sims[s] = mean over D of src_w * valid
        if (lane == 0)
            out[OFF_WT + s * kHW + p] = srcw * (float)__popc(vmask) * (1.f / kD);
    }

    // ---------------- final per-pixel stage ----------------
    float hmin = dec_f(g_min_enc), hmax = dec_f(g_max_enc);
    float nh_lane = (dep_lane - hmin) / (hmax - hmin);

    // qv tree summed over 32 lanes = 4x the 8-group sum -> *0.25
    // precise two-step division matching reference (/sum_weight then /cor_weight_sum)
    float logit_lane = (Lacc * 0.25f / sumw_lane) / cws_lane + nh_lane;

    // softmax over depth (precise; once per pixel)
    float m2 = logit_lane;
#pragma unroll
    for (int off = 16; off > 0; off >>= 1)
        m2 = fmaxf(m2, __shfl_xor_sync(FULL, m2, off));
    float e2 = expf(logit_lane - m2);
    float den2 = e2;
#pragma unroll
    for (int off = 16; off > 0; off >>= 1)
        den2 += __shfl_xor_sync(FULL, den2, off);
    float aw = e2 / den2;
    out[OFF_ATTN + lane * kHW + p] = aw;
    out[OFF_NV + lane * kHW + p] = nv_lane;

    // argmax (first index on tie, matching jnp.argmax)
    float bv = aw; int bi = lane;
#pragma unroll
    for (int off = 16; off > 0; off >>= 1) {
        float ov = __shfl_xor_sync(FULL, bv, off);
        int oi = __shfl_xor_sync(FULL, bi, off);
        if (ov > bv || (ov == bv && oi < bi)) { bv = ov; bi = oi; }
    }
    float depth = __shfl_sync(FULL, dep_lane, bi);
    float d0 = __shfl_sync(FULL, dep_lane, 0);
    float d1 = __shfl_sync(FULL, dep_lane, 1);
    float sw0 = __shfl_sync(FULL, sumw_lane, 0);
    if (lane == 0) {
        out[OFF_DEPTH + p] = depth;
        out[OFF_CONF + p] = bv;
        out[OFF_SW + p] = sw0 * 0.25f;   // / nsrc
        float itv = d1 - d0;
        out[OFF_MIN + p] = depth - itv;
        out[OFF_MAX + p] = depth + itv;
    }
    if (lane < 3) {
        out[OFF_EN + lane * kHW + p] =
            w_norm[lane*3+0]*np0 + w_norm[lane*3+1]*np1 + w_norm[lane*3+2]*np2;
    }
}

// ---------------------------------------------------------------------------
extern "C" void kernel_launch(void* const* d_in, const int* in_sizes, int n_in,
                              void* d_out, int out_size) {
    const float* ref   = (const float*)d_in[0];  // (1,32,192,192)
    const float* src   = (const float*)d_in[1];  // (4,1,32,192,192)
    const float* rotn  = (const float*)d_in[2];  // (1,5,3,3)
    const float* normp = (const float*)d_in[3];  // (1,3,192,192)
    const float* projm = (const float*)d_in[4];  // (1,5,2,4,4)
    const float* dhypo = (const float*)d_in[5];  // (1,32,192,192)
    const float* wreg  = (const float*)d_in[6];  // (8,)
    const float* wnorm = (const float*)d_in[7];  // (3,3)
    float* out = (float*)d_out;

    setup_kernel<<<1, 1>>>(rotn, projm);
    dim3 tb(32, 32);
    dim3 tg(kW / 32, kH, 5);
    transpose_kernel<<<tg, tb>>>(ref, src);
    minmax_kernel<<<256, 256>>>(dhypo);
    main_kernel<<<kHW / 4, 128>>>(normp, dhypo, wreg, wnorm, out);
}

// round 14
// speedup vs baseline: 1.8986x; 1.1574x over previous
#include <cuda_runtime.h>
#include <math.h>

// ---------------------------------------------------------------------------
// Problem constants
// ---------------------------------------------------------------------------
namespace {
constexpr int kC = 32, kG = 8, kD = 32, kH = 192, kW = 192;
constexpr int kHW = kH * kW;
constexpr int kNS = 4;   // nsrc = V-1

// output layout (concatenated tuple, all f32)
constexpr int OFF_DEPTH = 0;
constexpr int OFF_CONF  = OFF_DEPTH + kHW;
constexpr int OFF_ATTN  = OFF_CONF + kHW;            // (D,H,W)
constexpr int OFF_EN    = OFF_ATTN + kD * kHW;       // (3,H,W)
constexpr int OFF_SW    = OFF_EN + 3 * kHW;          // (H,W)
constexpr int OFF_WT    = OFF_SW + kHW;              // (NS,H,W)
constexpr int OFF_NV    = OFF_WT + kNS * kHW;        // (D,H,W)
constexpr int OFF_MIN   = OFF_NV + kD * kHW;         // (H,W)
constexpr int OFF_MAX   = OFF_MIN + kHW;             // (H,W)
}

// ---------------------------------------------------------------------------
// Scratch (static __device__ arrays: no allocation allowed)
// ---------------------------------------------------------------------------
__device__ float g_ref_t[kHW * kC];              // ref features (H,W,C)
__device__ float g_src_t[kNS * kHW * kC];        // src features (ns,H,W,C)
__device__ float g_rot[kNS * 9];
__device__ float g_trans[kNS * 3];
__device__ float g_norv[kNS * 3];
__device__ unsigned g_min_enc, g_max_enc;

// order-preserving float<->uint encoding (for atomic min/max)
__device__ __forceinline__ unsigned enc_f(float x) {
    unsigned u = __float_as_uint(x);
    return (u & 0x80000000u) ? ~u : (u | 0x80000000u);
}
__device__ __forceinline__ float dec_f(unsigned u) {
    return (u & 0x80000000u) ? __uint_as_float(u & 0x7FFFFFFFu)
                             : __uint_as_float(~u);
}

// ---------------------------------------------------------------------------
// Setup: projection matrices, relative rotations, min/max init (1 thread)
// ---------------------------------------------------------------------------
__device__ void inv3(const double* a, double* o) {
    double c00 =   a[4]*a[8] - a[5]*a[7];
    double c01 = -(a[3]*a[8] - a[5]*a[6]);
    double c02 =   a[3]*a[7] - a[4]*a[6];
    double det = a[0]*c00 + a[1]*c01 + a[2]*c02;
    double id = 1.0 / det;
    o[0] =  c00 * id;
    o[1] = -(a[1]*a[8] - a[2]*a[7]) * id;
    o[2] =  (a[1]*a[5] - a[2]*a[4]) * id;
    o[3] =  c01 * id;
    o[4] =  (a[0]*a[8] - a[2]*a[6]) * id;
    o[5] = -(a[0]*a[5] - a[2]*a[3]) * id;
    o[6] =  c02 * id;
    o[7] = -(a[0]*a[7] - a[1]*a[6]) * id;
    o[8] =  (a[0]*a[4] - a[1]*a[3]) * id;
}
__device__ void mm3(const double* a, const double* b, double* o) {
    for (int r = 0; r < 3; r++)
        for (int c = 0; c < 3; c++)
            o[r*3+c] = a[r*3]*b[c] + a[r*3+1]*b[3+c] + a[r*3+2]*b[6+c];
}

__global__ void setup_kernel(const float* __restrict__ rotation,
                             const float* __restrict__ proj) {
    if (threadIdx.x != 0 || blockIdx.x != 0) return;
    g_min_enc = 0xFFFFFFFFu;
    g_max_enc = 0u;
    // proj layout: (1, 5, 2, 4, 4) : [view][E|K][4][4]
    // M_v = K33 @ E33 ; t_v = K33 @ E[:3,3]
    double M[5][9], t[5][3];
    for (int v = 0; v < 5; v++) {
        const float* E = proj + v * 32;
        const float* K = proj + v * 32 + 16;
        for (int r = 0; r < 3; r++) {
            for (int c = 0; c < 3; c++) {
                double s = 0.0;
                for (int k = 0; k < 3; k++) s += (double)K[r*4+k] * (double)E[k*4+c];
                M[v][r*3+c] = s;
            }
            double s = 0.0;
            for (int k = 0; k < 3; k++) s += (double)K[r*4+k] * (double)E[k*4+3];
            t[v][r] = s;
        }
    }
    double MrI[9]; inv3(M[0], MrI);
    double R0[9];  for (int i = 0; i < 9; i++) R0[i] = (double)rotation[i];
    double R0I[9]; inv3(R0, R0I);
    for (int s = 0; s < kNS; s++) {
        int v = s + 1;
        // proj = src_new @ inv(ref_new): rot = Ms Mr^-1, trans = ts - rot tr
        double R[9]; mm3(M[v], MrI, R);
        for (int i = 0; i < 9; i++) g_rot[s*9+i] = (float)R[i];
        for (int r = 0; r < 3; r++) {
            double tr = t[v][r];
            for (int c = 0; c < 3; c++) tr -= R[r*3+c] * t[0][c];
            g_trans[s*3+r] = (float)tr;
        }
        // norv = row 2 of (R_v @ R_0^-1)
        double Rv[9]; for (int i = 0; i < 9; i++) Rv[i] = (double)rotation[v*9+i];
        double Rel[9]; mm3(Rv, R0I, Rel);
        for (int c = 0; c < 3; c++) g_norv[s*3+c] = (float)Rel[6+c];
    }
}

// ---------------------------------------------------------------------------
// Transpose features (C,H,W) -> (H,W,C), 5 views. Coalesced both sides.
// ---------------------------------------------------------------------------
__global__ void transpose_kernel(const float* __restrict__ ref,
                                 const float* __restrict__ src) {
    __shared__ float tile[32][33];
    int v = blockIdx.z;
    const float* in = (v == 0) ? ref : (src + (size_t)(v - 1) * kC * kHW);
    float* out = (v == 0) ? g_ref_t : (g_src_t + (size_t)(v - 1) * kHW * kC);
    int wbase = blockIdx.x * 32;
    int h = blockIdx.y;
    int tx = threadIdx.x, ty = threadIdx.y;   // ty = channel on read
    tile[ty][tx] = in[(size_t)ty * kHW + h * kW + wbase + tx];
    __syncthreads();
    out[(size_t)(h * kW + wbase + ty) * kC + tx] = tile[tx][ty];
}

// ---------------------------------------------------------------------------
// hmin / hmax reduction over depth_hypo
// ---------------------------------------------------------------------------
__global__ void minmax_kernel(const float* __restrict__ dh) {
    __shared__ unsigned smn[256], smx[256];
    unsigned lmn = 0xFFFFFFFFu, lmx = 0u;
    for (int i = blockIdx.x * blockDim.x + threadIdx.x; i < kD * kHW;
         i += gridDim.x * blockDim.x) {
        unsigned e = enc_f(dh[i]);
        lmn = min(lmn, e);
        lmx = max(lmx, e);
    }
    smn[threadIdx.x] = lmn; smx[threadIdx.x] = lmx;
    __syncthreads();
    for (int s = 128; s > 0; s >>= 1) {
        if (threadIdx.x < s) {
            smn[threadIdx.x] = min(smn[threadIdx.x], smn[threadIdx.x + s]);
            smx[threadIdx.x] = max(smx[threadIdx.x], smx[threadIdx.x + s]);
        }
        __syncthreads();
    }
    if (threadIdx.x == 0) {
        atomicMin(&g_min_enc, smn[0]);
        atomicMax(&g_max_enc, smx[0]);
    }
}

// ---------------------------------------------------------------------------
// Main fused kernel: one warp per pixel, lane = channel (C=32), D=32=warpSize
//
// Per source, lane l precomputes its own depth-l sample descriptor:
// validity-folded bilinear tap weights (separable: e.g. w00 = owxe*owye with
// owxe=bx0?1-wx:0 ...) + clamped base / tap offsets. Stored in smem (32B),
// fetched per depth iteration with 2 uniform LDS.128 (replaces 5 SHFLs).
// Reductions use the full-warp identity:
//   ts = Sum_l acc_l*refc4_l,  qv = Sum_l acc_l*refc4_l*wreg_{g(l)}
// computed together via pair-fold + bit0-split tree (6 shfls total).
// ---------------------------------------------------------------------------
struct Desc { float4 w; int4 a; };   // w00,w01,w10,w11 | a00, offx, offy, pad

__global__ __launch_bounds__(128, 8) void main_kernel(
    const float* __restrict__ normal_plane,
    const float* __restrict__ depth_hypo,
    const float* __restrict__ w_reg,
    const float* __restrict__ w_norm,
    float* __restrict__ out)
{
    const unsigned FULL = 0xFFFFFFFFu;
    __shared__ Desc sdesc[4][kD];
    int wid = threadIdx.x >> 5;
    int p = blockIdx.x * 4 + wid;
    int lane = threadIdx.x & 31;
    bool oddlane = (lane & 1);
    float xf = (float)(p % kW), yf = (float)(p / kW);

    float refc4 = g_ref_t[p * kC + lane] * 0.25f;  // ref feature * 1/4 (group mean prefold)
    float np0 = normal_plane[p];
    float np1 = normal_plane[kHW + p];
    float np2 = normal_plane[2 * kHW + p];
    float wreg_g = w_reg[lane >> 2];
    float dep_lane = depth_hypo[lane * kHW + p];   // lane l holds depth l

    float Lacc      = 0.f;     // numerator of attn logit, d = lane
    float cws_lane  = 1e-8f;   // cor_weight_sum[d=lane]
    float sumw_lane = 1e-8f;   // sum_weight[d=lane]
    float nv_lane   = 0.f;     // num_valid[d=lane]

#pragma unroll 1
    for (int s = 0; s < kNS; s++) {
        const float* srcL = g_src_t + s * (kHW * kC) + lane;
        float nv0 = g_norv[s*3+0], nv1 = g_norv[s*3+1], nv2 = g_norv[s*3+2];
        float srcw = fmaxf(np0*nv0 + np1*nv1 + np2*nv2, 0.f) + 0.01f;

        // ---- per-lane projection precompute (my depth = lane) ----
        {
            float r00 = g_rot[s*9+0], r01 = g_rot[s*9+1], r02 = g_rot[s*9+2];
            float r10 = g_rot[s*9+3], r11 = g_rot[s*9+4], r12 = g_rot[s*9+5];
            float r20 = g_rot[s*9+6], r21 = g_rot[s*9+7], r22 = g_rot[s*9+8];
            float trx = g_trans[s*3+0], try_ = g_trans[s*3+1], trz = g_trans[s*3+2];
            float rx = r00*xf + r01*yf + r02;
            float ry = r10*xf + r11*yf + r12;
            float rz = r20*xf + r21*yf + r22;
            float X = fmaf(rx, dep_lane, trx);
            float Y = fmaf(ry, dep_lane, try_);
            float Z = fmaf(rz, dep_lane, trz);
            if (Z == 0.f) Z = 1e-9f;
            float rZ = __fdividef(1.f, Z);
            // clamp to avoid int overflow; preserves in/out-of-bounds semantics
            float px = fminf(fmaxf(X * rZ, -4.f), (float)kW + 4.f);
            float py = fminf(fmaxf(Y * rZ, -4.f), (float)kH + 4.f);
            float x0f = floorf(px), y0f = floorf(py);
            float wx = px - x0f, wy = py - y0f;
            int x0 = (int)x0f, y0 = (int)y0f;
            int x1 = x0 + 1, y1 = y0 + 1;
            // validity folded into separable tap weights (matches reference
            // clip-index + zero-weight semantics exactly)
            float owxe = ((unsigned)x0 < (unsigned)kW) ? (1.f - wx) : 0.f;
            float wxe  = ((unsigned)x1 < (unsigned)kW) ? wx : 0.f;
            float owye = ((unsigned)y0 < (unsigned)kH) ? (1.f - wy) : 0.f;
            float wye  = ((unsigned)y1 < (unsigned)kH) ? wy : 0.f;
            int xc0 = min(max(x0, 0), kW - 1), xc1 = min(max(x1, 0), kW - 1);
            int yc0 = min(max(y0, 0), kH - 1), yc1 = min(max(y1, 0), kH - 1);
            Desc d;
            d.w = make_float4(owxe * owye, wxe * owye, owxe * wye, wxe * wye);
            d.a = make_int4((yc0 * kW + xc0) * kC,
                            (xc1 - xc0) * kC,
                            (yc1 - yc0) * (kW * kC), 0);
            sdesc[wid][lane] = d;
        }
        __syncwarp();

        float den = 0.f;       // per-src softmax denominator (max-free; logits O(10))
        float my_e = 0.f;      // e_d at d == lane
        float P = 0.f;         // e_d * qv_d at d == lane (validity applied post-loop)
        unsigned vmask = 0u;   // valid bits, built on lane 0 only

#pragma unroll
        for (int d = 0; d < kD; d++) {
            float4 w = sdesc[wid][d].w;     // uniform LDS.128 (broadcast)
            int4   a = sdesc[wid][d].a;     // uniform LDS.128 (broadcast)
            float f00 = srcL[a.x];
            float f01 = srcL[a.x + a.y];
            float f10 = srcL[a.x + a.z];
            float f11 = srcL[a.x + a.y + a.z];
            float acc = w.x * f00;
            acc = fmaf(w.y, f01, acc);
            acc = fmaf(w.z, f10, acc);
            acc = fmaf(w.w, f11, acc);
            // validity bit on lane 0 only (channel 0); broadcast after the loop
            if (lane == 0) vmask |= (acc != 0.f) ? (1u << d) : 0u;
            // pair fold: s1 = pair-sum of acc*refc4 (wreg is pair-constant)
            float s1 = acc * refc4;
            s1 += __shfl_xor_sync(FULL, s1, 1);
            // bit0-split tree computes ts (even) and qv (odd) simultaneously
            float u = oddlane ? s1 * wreg_g : s1;
            u += __shfl_xor_sync(FULL, u, 2);
            u += __shfl_xor_sync(FULL, u, 4);
            u += __shfl_xor_sync(FULL, u, 8);
            u += __shfl_xor_sync(FULL, u, 16);
            float cr = __shfl_xor_sync(FULL, u, 1);
            float ts = oddlane ? cr : u;    // Sum_g cfd_g (softmax logit)
            float qv = oddlane ? u : cr;    // Sum_g wreg_g*cfd_g (attn numerator)
            float e = __expf(ts);   // logits O(+-10): no max-subtract needed
            den += e;
            if (lane == d) {
                my_e = e;
                P = e * qv;
            }
        }
        vmask = __shfl_sync(FULL, vmask, 0);

        float factor = 0.17677669529663687f / den;  // (1/sqrt(C)) / den  (precise)
        cws_lane += my_e * factor;
        float mybit = (float)((vmask >> lane) & 1u);
        sumw_lane += srcw * mybit;
        nv_lane += mybit;
        Lacc = fmaf(P * mybit, factor * srcw, Lacc);
        // sims[s] = mean over D of src_w * valid
        if (lane == 0)
            out[OFF_WT + s * kHW + p] = srcw * (float)__popc(vmask) * (1.f / kD);
    }

    // ---------------- final per-pixel stage ----------------
    float hmin = dec_f(g_min_enc), hmax = dec_f(g_max_enc);
    float nh_lane = (dep_lane - hmin) / (hmax - hmin);

    // qv counts each group exactly once -> NO 0.25 here (R9-R13 had a stale 4x
    // compensation carried from the 32-lane-tree formulation)
    float logit_lane = (Lacc / sumw_lane) / cws_lane + nh_lane;

    // softmax over depth (precise; once per pixel)
    float m2 = logit_lane;
#pragma unroll
    for (int off = 16; off > 0; off >>= 1)
        m2 = fmaxf(m2, __shfl_xor_sync(FULL, m2, off));
    float e2 = expf(logit_lane - m2);
    float den2 = e2;
#pragma unroll
    for (int off = 16; off > 0; off >>= 1)
        den2 += __shfl_xor_sync(FULL, den2, off);
    float aw = e2 / den2;
    out[OFF_ATTN + lane * kHW + p] = aw;
    out[OFF_NV + lane * kHW + p] = nv_lane;

    // argmax (first index on tie, matching jnp.argmax)
    float bv = aw; int bi = lane;
#pragma unroll
    for (int off = 16; off > 0; off >>= 1) {
        float ov = __shfl_xor_sync(FULL, bv, off);
        int oi = __shfl_xor_sync(FULL, bi, off);
        if (ov > bv || (ov == bv && oi < bi)) { bv = ov; bi = oi; }
    }
    float depth = __shfl_sync(FULL, dep_lane, bi);
    float d0 = __shfl_sync(FULL, dep_lane, 0);
    float d1 = __shfl_sync(FULL, dep_lane, 1);
    float sw0 = __shfl_sync(FULL, sumw_lane, 0);
    if (lane == 0) {
        out[OFF_DEPTH + p] = depth;
        out[OFF_CONF + p] = bv;
        out[OFF_SW + p] = sw0 * 0.25f;   // / nsrc
        float itv = d1 - d0;
        out[OFF_MIN + p] = depth - itv;
        out[OFF_MAX + p] = depth + itv;
    }
    if (lane < 3) {
        out[OFF_EN + lane * kHW + p] =
            w_norm[lane*3+0]*np0 + w_norm[lane*3+1]*np1 + w_norm[lane*3+2]*np2;
    }
}

// ---------------------------------------------------------------------------
extern "C" void kernel_launch(void* const* d_in, const int* in_sizes, int n_in,
                              void* d_out, int out_size) {
    const float* ref   = (const float*)d_in[0];  // (1,32,192,192)
    const float* src   = (const float*)d_in[1];  // (4,1,32,192,192)
    const float* rotn  = (const float*)d_in[2];  // (1,5,3,3)
    const float* normp = (const float*)d_in[3];  // (1,3,192,192)
    const float* projm = (const float*)d_in[4];  // (1,5,2,4,4)
    const float* dhypo = (const float*)d_in[5];  // (1,32,192,192)
    const float* wreg  = (const float*)d_in[6];  // (8,)
    const float* wnorm = (const float*)d_in[7];  // (3,3)
    float* out = (float*)d_out;

    setup_kernel<<<1, 1>>>(rotn, projm);
    dim3 tb(32, 32);
    dim3 tg(kW / 32, kH, 5);
    transpose_kernel<<<tg, tb>>>(ref, src);
    minmax_kernel<<<1024, 256>>>(dhypo);
    main_kernel<<<kHW / 4, 128>>>(normp, dhypo, wreg, wnorm, out);
}

// round 16
// speedup vs baseline: 1.9600x; 1.0323x over previous
#include <cuda_runtime.h>
#include <math.h>

// ---------------------------------------------------------------------------
// Problem constants
// ---------------------------------------------------------------------------
namespace {
constexpr int kC = 32, kG = 8, kD = 32, kH = 192, kW = 192;
constexpr int kHW = kH * kW;
constexpr int kNS = 4;   // nsrc = V-1

// output layout (concatenated tuple, all f32)
constexpr int OFF_DEPTH = 0;
constexpr int OFF_CONF  = OFF_DEPTH + kHW;
constexpr int OFF_ATTN  = OFF_CONF + kHW;            // (D,H,W)
constexpr int OFF_EN    = OFF_ATTN + kD * kHW;       // (3,H,W)
constexpr int OFF_SW    = OFF_EN + 3 * kHW;          // (H,W)
constexpr int OFF_WT    = OFF_SW + kHW;              // (NS,H,W)
constexpr int OFF_NV    = OFF_WT + kNS * kHW;        // (D,H,W)
constexpr int OFF_MIN   = OFF_NV + kD * kHW;         // (H,W)
constexpr int OFF_MAX   = OFF_MIN + kHW;             // (H,W)
}

// ---------------------------------------------------------------------------
// Scratch (static __device__ arrays: no allocation allowed)
// ---------------------------------------------------------------------------
__device__ float g_ref_t[kHW * kC];              // ref features (H,W,C)
__device__ float g_src_t[kNS * kHW * kC];        // src features (ns,H,W,C)
__device__ float g_rot[kNS * 9];
__device__ float g_trans[kNS * 3];
__device__ float g_norv[kNS * 3];
__device__ unsigned g_min_enc, g_max_enc;

// order-preserving float<->uint encoding (for atomic min/max)
__device__ __forceinline__ unsigned enc_f(float x) {
    unsigned u = __float_as_uint(x);
    return (u & 0x80000000u) ? ~u : (u | 0x80000000u);
}
__device__ __forceinline__ float dec_f(unsigned u) {
    return (u & 0x80000000u) ? __uint_as_float(u & 0x7FFFFFFFu)
                             : __uint_as_float(~u);
}

// ---------------------------------------------------------------------------
// Setup: projection matrices, relative rotations, min/max init (1 thread)
// ---------------------------------------------------------------------------
__device__ void inv3(const double* a, double* o) {
    double c00 =   a[4]*a[8] - a[5]*a[7];
    double c01 = -(a[3]*a[8] - a[5]*a[6]);
    double c02 =   a[3]*a[7] - a[4]*a[6];
    double det = a[0]*c00 + a[1]*c01 + a[2]*c02;
    double id = 1.0 / det;
    o[0] =  c00 * id;
    o[1] = -(a[1]*a[8] - a[2]*a[7]) * id;
    o[2] =  (a[1]*a[5] - a[2]*a[4]) * id;
    o[3] =  c01 * id;
    o[4] =  (a[0]*a[8] - a[2]*a[6]) * id;
    o[5] = -(a[0]*a[5] - a[2]*a[3]) * id;
    o[6] =  c02 * id;
    o[7] = -(a[0]*a[7] - a[1]*a[6]) * id;
    o[8] =  (a[0]*a[4] - a[1]*a[3]) * id;
}
__device__ void mm3(const double* a, const double* b, double* o) {
    for (int r = 0; r < 3; r++)
        for (int c = 0; c < 3; c++)
            o[r*3+c] = a[r*3]*b[c] + a[r*3+1]*b[3+c] + a[r*3+2]*b[6+c];
}

__global__ void setup_kernel(const float* __restrict__ rotation,
                             const float* __restrict__ proj) {
    if (threadIdx.x != 0 || blockIdx.x != 0) return;
    g_min_enc = 0xFFFFFFFFu;
    g_max_enc = 0u;
    // proj layout: (1, 5, 2, 4, 4) : [view][E|K][4][4]
    // M_v = K33 @ E33 ; t_v = K33 @ E[:3,3]
    double M[5][9], t[5][3];
    for (int v = 0; v < 5; v++) {
        const float* E = proj + v * 32;
        const float* K = proj + v * 32 + 16;
        for (int r = 0; r < 3; r++) {
            for (int c = 0; c < 3; c++) {
                double s = 0.0;
                for (int k = 0; k < 3; k++) s += (double)K[r*4+k] * (double)E[k*4+c];
                M[v][r*3+c] = s;
            }
            double s = 0.0;
            for (int k = 0; k < 3; k++) s += (double)K[r*4+k] * (double)E[k*4+3];
            t[v][r] = s;
        }
    }
    double MrI[9]; inv3(M[0], MrI);
    double R0[9];  for (int i = 0; i < 9; i++) R0[i] = (double)rotation[i];
    double R0I[9]; inv3(R0, R0I);
    for (int s = 0; s < kNS; s++) {
        int v = s + 1;
        // proj = src_new @ inv(ref_new): rot = Ms Mr^-1, trans = ts - rot tr
        double R[9]; mm3(M[v], MrI, R);
        for (int i = 0; i < 9; i++) g_rot[s*9+i] = (float)R[i];
        for (int r = 0; r < 3; r++) {
            double tr = t[v][r];
            for (int c = 0; c < 3; c++) tr -= R[r*3+c] * t[0][c];
            g_trans[s*3+r] = (float)tr;
        }
        // norv = row 2 of (R_v @ R_0^-1)
        double Rv[9]; for (int i = 0; i < 9; i++) Rv[i] = (double)rotation[v*9+i];
        double Rel[9]; mm3(Rv, R0I, Rel);
        for (int c = 0; c < 3; c++) g_norv[s*3+c] = (float)Rel[6+c];
    }
}

// ---------------------------------------------------------------------------
// Transpose features (C,H,W) -> (H,W,C), 5 views. Coalesced both sides.
// ---------------------------------------------------------------------------
__global__ void transpose_kernel(const float* __restrict__ ref,
                                 const float* __restrict__ src) {
    __shared__ float tile[32][33];
    int v = blockIdx.z;
    const float* in = (v == 0) ? ref : (src + (size_t)(v - 1) * kC * kHW);
    float* out = (v == 0) ? g_ref_t : (g_src_t + (size_t)(v - 1) * kHW * kC);
    int wbase = blockIdx.x * 32;
    int h = blockIdx.y;
    int tx = threadIdx.x, ty = threadIdx.y;   // ty = channel on read
    tile[ty][tx] = in[(size_t)ty * kHW + h * kW + wbase + tx];
    __syncthreads();
    out[(size_t)(h * kW + wbase + ty) * kC + tx] = tile[tx][ty];
}

// ---------------------------------------------------------------------------
// hmin / hmax reduction over depth_hypo
// ---------------------------------------------------------------------------
__global__ void minmax_kernel(const float* __restrict__ dh) {
    __shared__ unsigned smn[256], smx[256];
    unsigned lmn = 0xFFFFFFFFu, lmx = 0u;
    for (int i = blockIdx.x * blockDim.x + threadIdx.x; i < kD * kHW;
         i += gridDim.x * blockDim.x) {
        unsigned e = enc_f(dh[i]);
        lmn = min(lmn, e);
        lmx = max(lmx, e);
    }
    smn[threadIdx.x] = lmn; smx[threadIdx.x] = lmx;
    __syncthreads();
    for (int s = 128; s > 0; s >>= 1) {
        if (threadIdx.x < s) {
            smn[threadIdx.x] = min(smn[threadIdx.x], smn[threadIdx.x + s]);
            smx[threadIdx.x] = max(smx[threadIdx.x], smx[threadIdx.x + s]);
        }
        __syncthreads();
    }
    if (threadIdx.x == 0) {
        atomicMin(&g_min_enc, smn[0]);
        atomicMax(&g_max_enc, smx[0]);
    }
}

// ---------------------------------------------------------------------------
// Main fused kernel: one warp per pixel, D=32=warpSize
//
// Two lane roles:
//  * precompute + epilogue: lane = depth (descriptor for its own depth;
//    validity = (sum of 4 tap weights != 0), exact for nonneg weights and
//    measure-zero-equivalent to (warped_ch0 != 0) for continuous features)
//  * depth loop: lane = tx*16 + cp; lane handles channels {2cp, 2cp+1} for
//    x-tap tx -> two float2 LDG.64 per iter (replaces four LDG.32).
// Reductions (full-warp identities, pair-trick tree, 6 shfls):
//   ts = Sum_ch acc_ch*refc4_ch,  qv = Sum_ch acc_ch*refc4_ch*wreg_{g(ch)}
// ---------------------------------------------------------------------------
struct Desc { float4 w; int4 a; };   // w00,w01,w10,w11 | a00, offx, offy, pad

__global__ __launch_bounds__(128, 8) void main_kernel(
    const float* __restrict__ normal_plane,
    const float* __restrict__ depth_hypo,
    const float* __restrict__ w_reg,
    const float* __restrict__ w_norm,
    float* __restrict__ out)
{
    const unsigned FULL = 0xFFFFFFFFu;
    __shared__ Desc sdesc[4][kD];
    int wid = threadIdx.x >> 5;
    int p = blockIdx.x * 4 + wid;
    int lane = threadIdx.x & 31;
    int tx = lane >> 4;          // x-tap half (depth-loop role)
    int cp = lane & 15;          // channel pair (depth-loop role)
    float xf = (float)(p % kW), yf = (float)(p / kW);

    // channel-pair ref features * 1/4 (group-mean prefold)
    float2 rc = ((const float2*)(g_ref_t + p * kC))[cp];
    rc.x *= 0.25f; rc.y *= 0.25f;
    float wreg_cp = w_reg[cp >> 1];              // group of channels 2cp,2cp+1

    float np0 = normal_plane[p];
    float np1 = normal_plane[kHW + p];
    float np2 = normal_plane[2 * kHW + p];
    float dep_lane = depth_hypo[lane * kHW + p];   // lane l holds depth l

    float Lacc      = 0.f;     // numerator of attn logit, d = lane
    float cws_lane  = 1e-8f;   // cor_weight_sum[d=lane]
    float sumw_lane = 1e-8f;   // sum_weight[d=lane]
    float nv_lane   = 0.f;     // num_valid[d=lane]

#pragma unroll 1
    for (int s = 0; s < kNS; s++) {
        const float* srcP = g_src_t + s * (kHW * kC) + 2 * cp;
        float nv0 = g_norv[s*3+0], nv1 = g_norv[s*3+1], nv2 = g_norv[s*3+2];
        float srcw = fmaxf(np0*nv0 + np1*nv1 + np2*nv2, 0.f) + 0.01f;

        // ---- per-lane projection precompute (my depth = lane) ----
        bool myvalid;
        __syncwarp();   // prior iteration's sdesc reads complete before rewrite
        {
            float r00 = g_rot[s*9+0], r01 = g_rot[s*9+1], r02 = g_rot[s*9+2];
            float r10 = g_rot[s*9+3], r11 = g_rot[s*9+4], r12 = g_rot[s*9+5];
            float r20 = g_rot[s*9+6], r21 = g_rot[s*9+7], r22 = g_rot[s*9+8];
            float trx = g_trans[s*3+0], try_ = g_trans[s*3+1], trz = g_trans[s*3+2];
            float rx = r00*xf + r01*yf + r02;
            float ry = r10*xf + r11*yf + r12;
            float rz = r20*xf + r21*yf + r22;
            float X = fmaf(rx, dep_lane, trx);
            float Y = fmaf(ry, dep_lane, try_);
            float Z = fmaf(rz, dep_lane, trz);
            if (Z == 0.f) Z = 1e-9f;
            float rZ = __fdividef(1.f, Z);
            // clamp to avoid int overflow; preserves in/out-of-bounds semantics
            float px = fminf(fmaxf(X * rZ, -4.f), (float)kW + 4.f);
            float py = fminf(fmaxf(Y * rZ, -4.f), (float)kH + 4.f);
            float x0f = floorf(px), y0f = floorf(py);
            float wx = px - x0f, wy = py - y0f;
            int x0 = (int)x0f, y0 = (int)y0f;
            int x1 = x0 + 1, y1 = y0 + 1;
            // validity folded into separable tap weights (matches reference
            // clip-index + zero-weight semantics exactly)
            float owxe = ((unsigned)x0 < (unsigned)kW) ? (1.f - wx) : 0.f;
            float wxe  = ((unsigned)x1 < (unsigned)kW) ? wx : 0.f;
            float owye = ((unsigned)y0 < (unsigned)kH) ? (1.f - wy) : 0.f;
            float wye  = ((unsigned)y1 < (unsigned)kH) ? wy : 0.f;
            int xc0 = min(max(x0, 0), kW - 1), xc1 = min(max(x1, 0), kW - 1);
            int yc0 = min(max(y0, 0), kH - 1), yc1 = min(max(y1, 0), kH - 1);
            Desc d;
            d.w = make_float4(owxe * owye, wxe * owye, owxe * wye, wxe * wye);
            d.a = make_int4((yc0 * kW + xc0) * kC,
                            (xc1 - xc0) * kC,
                            (yc1 - yc0) * (kW * kC), 0);
            sdesc[wid][lane] = d;
            // valid <=> some tap has nonzero weight (nonneg factors: exact)
            myvalid = ((owxe + wxe) * (owye + wye)) != 0.f;
        }
        __syncwarp();
        unsigned vmask = __ballot_sync(FULL, myvalid);  // bit d = depth d valid

        float den = 0.f;       // per-src softmax denominator (max-free; logits O(10))
        float my_e = 0.f;      // e_d at d == lane
        float P = 0.f;         // e_d * qv_d at d == lane

#pragma unroll
        for (int d = 0; d < kD; d++) {
            float4 w = sdesc[wid][d].w;     // uniform LDS.128 (broadcast)
            int4   a = sdesc[wid][d].a;     // uniform LDS.128 (broadcast)
            const float* pb = srcP + (a.x + (tx ? a.y : 0));
            float2 f0 = *(const float2*)(pb);          // y0 tap, my 2 channels
            float2 f1 = *(const float2*)(pb + a.z);    // y1 tap
            float wA = tx ? w.y : w.x;     // (x=tx, y0) weight
            float wB = tx ? w.w : w.z;     // (x=tx, y1) weight
            float alo = fmaf(wB, f1.x, wA * f0.x);   // partial acc, ch 2cp
            float ahi = fmaf(wB, f1.y, wA * f0.y);   // partial acc, ch 2cp+1
            float v = fmaf(ahi, rc.y, alo * rc.x);   // partial of Sum acc*refc4
            // pair-trick tree: ts on even lanes, qv on odd, then cross
            v += __shfl_xor_sync(FULL, v, 1);
            float u = (lane & 1) ? v * wreg_cp : v;
            u += __shfl_xor_sync(FULL, u, 2);
            u += __shfl_xor_sync(FULL, u, 4);
            u += __shfl_xor_sync(FULL, u, 8);
            u += __shfl_xor_sync(FULL, u, 16);
            float cr = __shfl_xor_sync(FULL, u, 1);
            float ts = (lane & 1) ? cr : u;    // Sum_g cfd_g (softmax logit)
            float qv = (lane & 1) ? u : cr;    // Sum_g wreg_g*cfd_g
            float e = __expf(ts);   // logits O(+-10): no max-subtract needed
            den += e;
            if (lane == d) {
                my_e = e;
                P = e * qv;
            }
        }

        float factor = 0.17677669529663687f / den;  // (1/sqrt(C)) / den  (precise)
        cws_lane += my_e * factor;
        float mybit = myvalid ? 1.f : 0.f;
        sumw_lane += srcw * mybit;
        nv_lane += mybit;
        Lacc = fmaf(P * mybit, factor * srcw, Lacc);
        // sims[s] = mean over D of src_w * valid
        if (lane == 0)
            out[OFF_WT + s * kHW + p] = srcw * (float)__popc(vmask) * (1.f / kD);
    }

    // ---------------- final per-pixel stage ----------------
    float hmin = dec_f(g_min_enc), hmax = dec_f(g_max_enc);
    float nh_lane = (dep_lane - hmin) / (hmax - hmin);

    float logit_lane = (Lacc / sumw_lane) / cws_lane + nh_lane;

    // softmax over depth (precise; once per pixel)
    float m2 = logit_lane;
#pragma unroll
    for (int off = 16; off > 0; off >>= 1)
        m2 = fmaxf(m2, __shfl_xor_sync(FULL, m2, off));
    float e2 = expf(logit_lane - m2);
    float den2 = e2;
#pragma unroll
    for (int off = 16; off > 0; off >>= 1)
        den2 += __shfl_xor_sync(FULL, den2, off);
    float aw = e2 / den2;
    out[OFF_ATTN + lane * kHW + p] = aw;
    out[OFF_NV + lane * kHW + p] = nv_lane;

    // argmax (first index on tie, matching jnp.argmax)
    float bv = aw; int bi = lane;
#pragma unroll
    for (int off = 16; off > 0; off >>= 1) {
        float ov = __shfl_xor_sync(FULL, bv, off);
        int oi = __shfl_xor_sync(FULL, bi, off);
        if (ov > bv || (ov == bv && oi < bi)) { bv = ov; bi = oi; }
    }
    float depth = __shfl_sync(FULL, dep_lane, bi);
    float d0 = __shfl_sync(FULL, dep_lane, 0);
    float d1 = __shfl_sync(FULL, dep_lane, 1);
    float sw0 = __shfl_sync(FULL, sumw_lane, 0);
    if (lane == 0) {
        out[OFF_DEPTH + p] = depth;
        out[OFF_CONF + p] = bv;
        out[OFF_SW + p] = sw0 * 0.25f;   // / nsrc
        float itv = d1 - d0;
        out[OFF_MIN + p] = depth - itv;
        out[OFF_MAX + p] = depth + itv;
    }
    if (lane < 3) {
        out[OFF_EN + lane * kHW + p] =
            w_norm[lane*3+0]*np0 + w_norm[lane*3+1]*np1 + w_norm[lane*3+2]*np2;
    }
}

// ---------------------------------------------------------------------------
extern "C" void kernel_launch(void* const* d_in, const int* in_sizes, int n_in,
                              void* d_out, int out_size) {
    const float* ref   = (const float*)d_in[0];  // (1,32,192,192)
    const float* src   = (const float*)d_in[1];  // (4,1,32,192,192)
    const float* rotn  = (const float*)d_in[2];  // (1,5,3,3)
    const float* normp = (const float*)d_in[3];  // (1,3,192,192)
    const float* projm = (const float*)d_in[4];  // (1,5,2,4,4)
    const float* dhypo = (const float*)d_in[5];  // (1,32,192,192)
    const float* wreg  = (const float*)d_in[6];  // (8,)
    const float* wnorm = (const float*)d_in[7];  // (3,3)
    float* out = (float*)d_out;

    setup_kernel<<<1, 1>>>(rotn, projm);
    dim3 tb(32, 32);
    dim3 tg(kW / 32, kH, 5);
    transpose_kernel<<<tg, tb>>>(ref, src);
    minmax_kernel<<<1024, 256>>>(dhypo);
    main_kernel<<<kHW / 4, 128>>>(normp, dhypo, wreg, wnorm, out);
}

// round 17
// speedup vs baseline: 2.3349x; 1.1913x over previous
#include <cuda_runtime.h>
#include <math.h>

// ---------------------------------------------------------------------------
// Problem constants
// ---------------------------------------------------------------------------
namespace {
constexpr int kC = 32, kG = 8, kD = 32, kH = 192, kW = 192;
constexpr int kHW = kH * kW;
constexpr int kNS = 4;   // nsrc = V-1

// output layout (concatenated tuple, all f32)
constexpr int OFF_DEPTH = 0;
constexpr int OFF_CONF  = OFF_DEPTH + kHW;
constexpr int OFF_ATTN  = OFF_CONF + kHW;            // (D,H,W)
constexpr int OFF_EN    = OFF_ATTN + kD * kHW;       // (3,H,W)
constexpr int OFF_SW    = OFF_EN + 3 * kHW;          // (H,W)
constexpr int OFF_WT    = OFF_SW + kHW;              // (NS,H,W)
constexpr int OFF_NV    = OFF_WT + kNS * kHW;        // (D,H,W)
constexpr int OFF_MIN   = OFF_NV + kD * kHW;         // (H,W)
constexpr int OFF_MAX   = OFF_MIN + kHW;             // (H,W)

constexpr int kRowBytes  = kW * kC * 4;              // 24576
constexpr int kPixBytes  = kC * 4;                   // 128
}

// ---------------------------------------------------------------------------
// Scratch (static __device__ arrays: no allocation allowed)
// ---------------------------------------------------------------------------
__device__ float g_ref_t[kHW * kC];              // ref features (H,W,C)
__device__ float g_src_t[kNS * kHW * kC];        // src features (ns,H,W,C)
__device__ float g_rot[kNS * 9];
__device__ float g_trans[kNS * 3];
__device__ float g_norv[kNS * 3];
__device__ unsigned g_min_enc, g_max_enc;

// order-preserving float<->uint encoding (for atomic min/max)
__device__ __forceinline__ unsigned enc_f(float x) {
    unsigned u = __float_as_uint(x);
    return (u & 0x80000000u) ? ~u : (u | 0x80000000u);
}
__device__ __forceinline__ float dec_f(unsigned u) {
    return (u & 0x80000000u) ? __uint_as_float(u & 0x7FFFFFFFu)
                             : __uint_as_float(~u);
}

// ---------------------------------------------------------------------------
// Setup: projection matrices, relative rotations, min/max init (1 thread)
// ---------------------------------------------------------------------------
__device__ void inv3(const double* a, double* o) {
    double c00 =   a[4]*a[8] - a[5]*a[7];
    double c01 = -(a[3]*a[8] - a[5]*a[6]);
    double c02 =   a[3]*a[7] - a[4]*a[6];
    double det = a[0]*c00 + a[1]*c01 + a[2]*c02;
    double id = 1.0 / det;
    o[0] =  c00 * id;
    o[1] = -(a[1]*a[8] - a[2]*a[7]) * id;
    o[2] =  (a[1]*a[5] - a[2]*a[4]) * id;
    o[3] =  c01 * id;
    o[4] =  (a[0]*a[8] - a[2]*a[6]) * id;
    o[5] = -(a[0]*a[5] - a[2]*a[3]) * id;
    o[6] =  c02 * id;
    o[7] = -(a[0]*a[7] - a[1]*a[6]) * id;
    o[8] =  (a[0]*a[4] - a[1]*a[3]) * id;
}
__device__ void mm3(const double* a, const double* b, double* o) {
    for (int r = 0; r < 3; r++)
        for (int c = 0; c < 3; c++)
            o[r*3+c] = a[r*3]*b[c] + a[r*3+1]*b[3+c] + a[r*3+2]*b[6+c];
}

__global__ void setup_kernel(const float* __restrict__ rotation,
                             const float* __restrict__ proj) {
    if (threadIdx.x != 0 || blockIdx.x != 0) return;
    g_min_enc = 0xFFFFFFFFu;
    g_max_enc = 0u;
    // proj layout: (1, 5, 2, 4, 4) : [view][E|K][4][4]
    // M_v = K33 @ E33 ; t_v = K33 @ E[:3,3]
    double M[5][9], t[5][3];
    for (int v = 0; v < 5; v++) {
        const float* E = proj + v * 32;
        const float* K = proj + v * 32 + 16;
        for (int r = 0; r < 3; r++) {
            for (int c = 0; c < 3; c++) {
                double s = 0.0;
                for (int k = 0; k < 3; k++) s += (double)K[r*4+k] * (double)E[k*4+c];
                M[v][r*3+c] = s;
            }
            double s = 0.0;
            for (int k = 0; k < 3; k++) s += (double)K[r*4+k] * (double)E[k*4+3];
            t[v][r] = s;
        }
    }
    double MrI[9]; inv3(M[0], MrI);
    double R0[9];  for (int i = 0; i < 9; i++) R0[i] = (double)rotation[i];
    double R0I[9]; inv3(R0, R0I);
    for (int s = 0; s < kNS; s++) {
        int v = s + 1;
        // proj = src_new @ inv(ref_new): rot = Ms Mr^-1, trans = ts - rot tr
        double R[9]; mm3(M[v], MrI, R);
        for (int i = 0; i < 9; i++) g_rot[s*9+i] = (float)R[i];
        for (int r = 0; r < 3; r++) {
            double tr = t[v][r];
            for (int c = 0; c < 3; c++) tr -= R[r*3+c] * t[0][c];
            g_trans[s*3+r] = (float)tr;
        }
        // norv = row 2 of (R_v @ R_0^-1)
        double Rv[9]; for (int i = 0; i < 9; i++) Rv[i] = (double)rotation[v*9+i];
        double Rel[9]; mm3(Rv, R0I, Rel);
        for (int c = 0; c < 3; c++) g_norv[s*3+c] = (float)Rel[6+c];
    }
}

// ---------------------------------------------------------------------------
// Transpose features (C,H,W) -> (H,W,C), 5 views. Coalesced both sides.
// ---------------------------------------------------------------------------
__global__ void transpose_kernel(const float* __restrict__ ref,
                                 const float* __restrict__ src) {
    __shared__ float tile[32][33];
    int v = blockIdx.z;
    const float* in = (v == 0) ? ref : (src + (size_t)(v - 1) * kC * kHW);
    float* out = (v == 0) ? g_ref_t : (g_src_t + (size_t)(v - 1) * kHW * kC);
    int wbase = blockIdx.x * 32;
    int h = blockIdx.y;
    int tx = threadIdx.x, ty = threadIdx.y;   // ty = channel on read
    tile[ty][tx] = in[(size_t)ty * kHW + h * kW + wbase + tx];
    __syncthreads();
    out[(size_t)(h * kW + wbase + ty) * kC + tx] = tile[tx][ty];
}

// ---------------------------------------------------------------------------
// hmin / hmax reduction over depth_hypo
// ---------------------------------------------------------------------------
__global__ void minmax_kernel(const float* __restrict__ dh) {
    __shared__ unsigned smn[256], smx[256];
    unsigned lmn = 0xFFFFFFFFu, lmx = 0u;
    for (int i = blockIdx.x * blockDim.x + threadIdx.x; i < kD * kHW;
         i += gridDim.x * blockDim.x) {
        unsigned e = enc_f(dh[i]);
        lmn = min(lmn, e);
        lmx = max(lmx, e);
    }
    smn[threadIdx.x] = lmn; smx[threadIdx.x] = lmx;
    __syncthreads();
    for (int s = 128; s > 0; s >>= 1) {
        if (threadIdx.x < s) {
            smn[threadIdx.x] = min(smn[threadIdx.x], smn[threadIdx.x + s]);
            smx[threadIdx.x] = max(smx[threadIdx.x], smx[threadIdx.x + s]);
        }
        __syncthreads();
    }
    if (threadIdx.x == 0) {
        atomicMin(&g_min_enc, smn[0]);
        atomicMax(&g_max_enc, smx[0]);
    }
}

// ---------------------------------------------------------------------------
// Main fused kernel: one warp per pixel, D=32=warpSize
//
// Roles:
//  * precompute + epilogue: lane = depth. Writes validity-folded separable
//    tap weights {owxe, wxe, owye, wye} (float4, smem) and a packed address
//    word base|dx<<24|dy<<25 (register, broadcast by shfl).
//  * depth loop: TWO depths per iteration. Half-warp h handles depth
//    da = 16h+it. Within a half: ty = lane&1 (y-tap row), cq = (lane>>1)&7
//    (channel quad). Each lane loads float4 taps for (ty, x0) and (ty, x1)
//    and dots them with its ref channel quad.
//  * reduction (within 16-lane half, 5 shfls for ts AND qv):
//    fold ty (xor1) -> split even/odd into ts/qv roles (wreg_cq) ->
//    fold cq (xor2,4,8) -> cross (xor1).
//  Lane l captures e/P for its own depth at it == (lane&15).
// ---------------------------------------------------------------------------
__global__ __launch_bounds__(128, 8) void main_kernel(
    const float* __restrict__ normal_plane,
    const float* __restrict__ depth_hypo,
    const float* __restrict__ w_reg,
    const float* __restrict__ w_norm,
    float* __restrict__ out)
{
    const unsigned FULL = 0xFFFFFFFFu;
    __shared__ float4 sw[4][kD];
    int wid = threadIdx.x >> 5;
    int p = blockIdx.x * 4 + wid;
    int lane = threadIdx.x & 31;
    int s4 = lane & 15;
    int hh = lane >> 4;          // half (high depth bit)
    int ty = s4 & 1;             // y-tap row (loop role)
    int cq = s4 >> 1;            // channel quad 0..7 (loop role)
    float xf = (float)(p % kW), yf = (float)(p / kW);

    // ref channel quad * 1/4 (group-mean prefold); group == cq
    float4 rc = ((const float4*)(g_ref_t + p * kC))[cq];
    rc.x *= 0.25f; rc.y *= 0.25f; rc.z *= 0.25f; rc.w *= 0.25f;
    float wreg_cq = w_reg[cq];

    float np0 = normal_plane[p];
    float np1 = normal_plane[kHW + p];
    float np2 = normal_plane[2 * kHW + p];
    float dep_lane = depth_hypo[lane * kHW + p];   // lane l holds depth l

    float Lacc      = 0.f;     // numerator of attn logit, d = lane
    float cws_lane  = 1e-8f;   // cor_weight_sum[d=lane]
    float sumw_lane = 1e-8f;   // sum_weight[d=lane]
    float nv_lane   = 0.f;     // num_valid[d=lane]

#pragma unroll 1
    for (int s = 0; s < kNS; s++) {
        const char* srcC = (const char*)g_src_t
                         + (size_t)s * (kHW * kC * 4) + cq * 16;
        float nv0 = g_norv[s*3+0], nv1 = g_norv[s*3+1], nv2 = g_norv[s*3+2];
        float srcw = fmaxf(np0*nv0 + np1*nv1 + np2*nv2, 0.f) + 0.01f;

        // ---- per-lane projection precompute (my depth = lane) ----
        bool myvalid;
        int addrpack;
        __syncwarp();   // prior iteration's sw reads complete before rewrite
        {
            float r00 = g_rot[s*9+0], r01 = g_rot[s*9+1], r02 = g_rot[s*9+2];
            float r10 = g_rot[s*9+3], r11 = g_rot[s*9+4], r12 = g_rot[s*9+5];
            float r20 = g_rot[s*9+6], r21 = g_rot[s*9+7], r22 = g_rot[s*9+8];
            float trx = g_trans[s*3+0], try_ = g_trans[s*3+1], trz = g_trans[s*3+2];
            float rx = r00*xf + r01*yf + r02;
            float ry = r10*xf + r11*yf + r12;
            float rz = r20*xf + r21*yf + r22;
            float X = fmaf(rx, dep_lane, trx);
            float Y = fmaf(ry, dep_lane, try_);
            float Z = fmaf(rz, dep_lane, trz);
            if (Z == 0.f) Z = 1e-9f;
            float rZ = __fdividef(1.f, Z);
            // clamp to avoid int overflow; preserves in/out-of-bounds semantics
            float px = fminf(fmaxf(X * rZ, -4.f), (float)kW + 4.f);
            float py = fminf(fmaxf(Y * rZ, -4.f), (float)kH + 4.f);
            float x0f = floorf(px), y0f = floorf(py);
            float wx = px - x0f, wy = py - y0f;
            int x0 = (int)x0f, y0 = (int)y0f;
            int x1 = x0 + 1, y1 = y0 + 1;
            // validity folded into separable tap weights (matches reference
            // clip-index + zero-weight semantics exactly)
            float owxe = ((unsigned)x0 < (unsigned)kW) ? (1.f - wx) : 0.f;
            float wxe  = ((unsigned)x1 < (unsigned)kW) ? wx : 0.f;
            float owye = ((unsigned)y0 < (unsigned)kH) ? (1.f - wy) : 0.f;
            float wye  = ((unsigned)y1 < (unsigned)kH) ? wy : 0.f;
            int xc0 = min(max(x0, 0), kW - 1), xc1 = min(max(x1, 0), kW - 1);
            int yc0 = min(max(y0, 0), kH - 1), yc1 = min(max(y1, 0), kH - 1);
            sw[wid][lane] = make_float4(owxe, wxe, owye, wye);
            addrpack = (yc0 * kW + xc0) * kPixBytes
                     | ((xc1 - xc0) << 24) | ((yc1 - yc0) << 25);
            // valid <=> some tap has nonzero weight (nonneg factors: exact)
            myvalid = ((owxe + wxe) * (owye + wye)) != 0.f;
        }
        __syncwarp();
        unsigned vmask = __ballot_sync(FULL, myvalid);  // bit d = depth d valid

        float den_h = 0.f;     // softmax denom, my half's depths
        float my_e = 0.f;      // e at my depth (lane = depth)
        float P = 0.f;         // e * qv at my depth

#pragma unroll
        for (int it = 0; it < 16; it++) {
            int da = (hh << 4) + it;                       // my half's depth
            int ad = __shfl_sync(FULL, addrpack, da);      // address pack
            float4 w4 = sw[wid][da];                       // uniform-per-half LDS.128
            int base = ad & 0x00FFFFFF;
            int dx128 = (ad >> 17) & 128;                  // dx ? 128 : 0
            int offy = (ty & (ad >> 25) & 1) ? kRowBytes : 0;
            const char* pb = srcC + base + offy;
            float4 f0 = *(const float4*)(pb);              // (x0, ty) tap
            float4 f1 = *(const float4*)(pb + dx128);      // (x1, ty) tap
            float d0 = fmaf(f0.w, rc.w, fmaf(f0.z, rc.z,
                       fmaf(f0.y, rc.y, f0.x * rc.x)));
            float d1 = fmaf(f1.w, rc.w, fmaf(f1.z, rc.z,
                       fmaf(f1.y, rc.y, f1.x * rc.x)));
            float ywe = ty ? w4.w : w4.z;
            float v = fmaf(w4.y, d1, w4.x * d0) * ywe;
            // fold y-tap pairs (bit0 of s4)
            v += __shfl_xor_sync(FULL, v, 1);
            // split roles: even s4 -> ts partial, odd s4 -> qv partial
            float u = ty ? v * wreg_cq : v;
            u += __shfl_xor_sync(FULL, u, 2);
            u += __shfl_xor_sync(FULL, u, 4);
            u += __shfl_xor_sync(FULL, u, 8);
            float cr = __shfl_xor_sync(FULL, u, 1);
            float ts = ty ? cr : u;        // Sum_g cfd_g (softmax logit)
            float qv = ty ? u : cr;        // Sum_g wreg_g*cfd_g
            float e = __expf(ts);          // logits O(+-10): no max-subtract
            den_h += e;
            if (s4 == it) { my_e = e; P = e * qv; }   // da == lane here
        }
        float den = den_h + __shfl_xor_sync(FULL, den_h, 16);  // both halves

        float factor = 0.17677669529663687f / den;  // (1/sqrt(C)) / den
        cws_lane += my_e * factor;
        float mybit = myvalid ? 1.f : 0.f;
        sumw_lane += srcw * mybit;
        nv_lane += mybit;
        Lacc = fmaf(P * mybit, factor * srcw, Lacc);
        // sims[s] = mean over D of src_w * valid
        if (lane == 0)
            out[OFF_WT + s * kHW + p] = srcw * (float)__popc(vmask) * (1.f / kD);
    }

    // ---------------- final per-pixel stage ----------------
    float hmin = dec_f(g_min_enc), hmax = dec_f(g_max_enc);
    float nh_lane = (dep_lane - hmin) / (hmax - hmin);

    float logit_lane = (Lacc / sumw_lane) / cws_lane + nh_lane;

    // softmax over depth (precise; once per pixel)
    float m2 = logit_lane;
#pragma unroll
    for (int off = 16; off > 0; off >>= 1)
        m2 = fmaxf(m2, __shfl_xor_sync(FULL, m2, off));
    float e2 = expf(logit_lane - m2);
    float den2 = e2;
#pragma unroll
    for (int off = 16; off > 0; off >>= 1)
        den2 += __shfl_xor_sync(FULL, den2, off);
    float aw = e2 / den2;
    out[OFF_ATTN + lane * kHW + p] = aw;
    out[OFF_NV + lane * kHW + p] = nv_lane;

    // argmax (first index on tie, matching jnp.argmax)
    float bv = aw; int bi = lane;
#pragma unroll
    for (int off = 16; off > 0; off >>= 1) {
        float ov = __shfl_xor_sync(FULL, bv, off);
        int oi = __shfl_xor_sync(FULL, bi, off);
        if (ov > bv || (ov == bv && oi < bi)) { bv = ov; bi = oi; }
    }
    float depth = __shfl_sync(FULL, dep_lane, bi);
    float d0 = __shfl_sync(FULL, dep_lane, 0);
    float d1 = __shfl_sync(FULL, dep_lane, 1);
    float sw0 = __shfl_sync(FULL, sumw_lane, 0);
    if (lane == 0) {
        out[OFF_DEPTH + p] = depth;
        out[OFF_CONF + p] = bv;
        out[OFF_SW + p] = sw0 * 0.25f;   // / nsrc
        float itv = d1 - d0;
        out[OFF_MIN + p] = depth - itv;
        out[OFF_MAX + p] = depth + itv;
    }
    if (lane < 3) {
        out[OFF_EN + lane * kHW + p] =
            w_norm[lane*3+0]*np0 + w_norm[lane*3+1]*np1 + w_norm[lane*3+2]*np2;
    }
}

// ---------------------------------------------------------------------------
extern "C" void kernel_launch(void* const* d_in, const int* in_sizes, int n_in,
                              void* d_out, int out_size) {
    const float* ref   = (const float*)d_in[0];  // (1,32,192,192)
    const float* src   = (const float*)d_in[1];  // (4,1,32,192,192)
    const float* rotn  = (const float*)d_in[2];  // (1,5,3,3)
    const float* normp = (const float*)d_in[3];  // (1,3,192,192)
    const float* projm = (const float*)d_in[4];  // (1,5,2,4,4)
    const float* dhypo = (const float*)d_in[5];  // (1,32,192,192)
    const float* wreg  = (const float*)d_in[6];  // (8,)
    const float* wnorm = (const float*)d_in[7];  // (3,3)
    float* out = (float*)d_out;

    setup_kernel<<<1, 1>>>(rotn, projm);
    dim3 tb(32, 32);
    dim3 tg(kW / 32, kH, 5);
    transpose_kernel<<<tg, tb>>>(ref, src);
    minmax_kernel<<<1024, 256>>>(dhypo);
    main_kernel<<<kHW / 4, 128>>>(normp, dhypo, wreg, wnorm, out);
}